// round 4
// baseline (speedup 1.0000x reference)
#include <cuda_runtime.h>
#include <math.h>

#define BATCH 8
#define SS 1048576              // 128*128*64
#define NTOT (BATCH * SS)       // 8388608 per component

// ---------------- scratch (device globals; no allocation) ----------------
__device__ float g_s_re[NTOT];
__device__ float g_s_im[NTOT];
__device__ float g_u_re[NTOT];
__device__ float g_u_im[NTOT];
__device__ float g_l_re[NTOT];
__device__ float g_l_im[NTOT];
__device__ float g_p_re[4194304];   // split-K partials (NC*B*d*d max)
__device__ float g_p_im[4194304];
__device__ float g_m_re[131072];    // routing matrix (B*d*d max)
__device__ float g_m_im[131072];

typedef unsigned long long u64;

// ---------------- f32x2 packed helpers ------------------------------------
__device__ __forceinline__ void fma2(u64& d, u64 a, u64 b) {
    asm("fma.rn.f32x2 %0, %1, %2, %3;" : "=l"(d) : "l"(a), "l"(b), "l"(d));
}
__device__ __forceinline__ void add2(u64& d, u64 a, u64 b) {
    asm("add.rn.f32x2 %0, %1, %2;" : "=l"(d) : "l"(a), "l"(b));
}
__device__ __forceinline__ void lds2(u64& lo, u64& hi, const float* p) {
    unsigned a = (unsigned)__cvta_generic_to_shared(p);
    asm volatile("ld.shared.v2.b64 {%0,%1}, [%2];" : "=l"(lo), "=l"(hi) : "r"(a));
}
__device__ __forceinline__ void unpack2(float& lo, float& hi, u64 v) {
    unsigned a, b;
    asm("mov.b64 {%0,%1}, %2;" : "=r"(a), "=r"(b) : "l"(v));
    lo = __uint_as_float(a); hi = __uint_as_float(b);
}

// ======================= NN kernel: C[b] = A(b?) * U[b] ====================
// tile: BM=64, BN=128, BK=16; 256 threads; per-thread 4(M) x 8(N)
// Karatsuba: T1=ar*br, T2=ai*bi, T3=(ar+ai)(br+bi); cr=T1-T2, ci=T3-T1-T2
#define NN_APAD 132     // 64 m-values duplicated -> 128 floats + 4 pad
#define NN_BPAD 136     // 128 cols + 8 pad

__global__ __launch_bounds__(256, 1)
void cgemm_nn(const float* __restrict__ Are, const float* __restrict__ Aim, int strideA,
              const float* __restrict__ Ure, const float* __restrict__ Uim,
              float* __restrict__ Cre, float* __restrict__ Cim,
              int d, int rest)
{
    __shared__ __align__(16) float Adr[16][NN_APAD], Adi[16][NN_APAD], Ads[16][NN_APAD];
    __shared__ __align__(16) float Bre[16][NN_BPAD], Bim[16][NN_BPAD];

    const int b  = blockIdx.z;
    const int m0 = blockIdx.y * 64;
    const int n0 = blockIdx.x * 128;

    const float* are = Are + (size_t)b * strideA;
    const float* aim = Aim + (size_t)b * strideA;
    const float* ure = Ure + (size_t)b * d * rest + n0;
    const float* uim = Uim + (size_t)b * d * rest + n0;
    float*       cre = Cre + (size_t)b * d * rest + n0;
    float*       cim = Cim + (size_t)b * d * rest + n0;

    const int tid = threadIdx.x;
    const int tn4 = (tid & 15) * 4;     // frag cols: [tn4..tn4+3] and [64+tn4..]
    const int tm  = tid >> 4;           // rows tm*4..tm*4+3
    const int tm8 = tm * 8;             // dup-offset into A rows
    const int brr = tid >> 4;           // B loader row 0..15
    const int bc4 = (tid & 15) * 4;     // B loader col
    const int arr = tid >> 2;           // A loader row 0..63
    const int ac4 = (tid & 3) * 4;      // A loader k-col

    u64 T1[4][4], T2[4][4], T3[4][4];
#pragma unroll
    for (int i = 0; i < 4; i++)
#pragma unroll
        for (int c = 0; c < 4; c++) { T1[i][c] = 0ULL; T2[i][c] = 0ULL; T3[i][c] = 0ULL; }

    // prefetch first tile
    float4 pb0r = *(const float4*)(ure + (size_t)brr * rest + bc4);
    float4 pb1r = *(const float4*)(ure + (size_t)brr * rest + 64 + bc4);
    float4 pb0i = *(const float4*)(uim + (size_t)brr * rest + bc4);
    float4 pb1i = *(const float4*)(uim + (size_t)brr * rest + 64 + bc4);
    float4 par  = *(const float4*)(are + (size_t)(m0 + arr) * d + ac4);
    float4 pai  = *(const float4*)(aim + (size_t)(m0 + arr) * d + ac4);

    for (int kk = 0; kk < d; kk += 16) {
        *(float4*)&Bre[brr][bc4]      = pb0r;
        *(float4*)&Bre[brr][64 + bc4] = pb1r;
        *(float4*)&Bim[brr][bc4]      = pb0i;
        *(float4*)&Bim[brr][64 + bc4] = pb1i;
        {
            const float* pr = (const float*)&par;
            const float* pi = (const float*)&pai;
#pragma unroll
            for (int j = 0; j < 4; j++) {
                float vr = pr[j], vi = pi[j];
                *(float2*)&Adr[ac4 + j][2 * arr] = make_float2(vr, vr);
                *(float2*)&Adi[ac4 + j][2 * arr] = make_float2(vi, vi);
                float vs = vr + vi;
                *(float2*)&Ads[ac4 + j][2 * arr] = make_float2(vs, vs);
            }
        }
        __syncthreads();

        if (kk + 16 < d) {
            pb0r = *(const float4*)(ure + (size_t)(kk + 16 + brr) * rest + bc4);
            pb1r = *(const float4*)(ure + (size_t)(kk + 16 + brr) * rest + 64 + bc4);
            pb0i = *(const float4*)(uim + (size_t)(kk + 16 + brr) * rest + bc4);
            pb1i = *(const float4*)(uim + (size_t)(kk + 16 + brr) * rest + 64 + bc4);
            par  = *(const float4*)(are + (size_t)(m0 + arr) * d + kk + 16 + ac4);
            pai  = *(const float4*)(aim + (size_t)(m0 + arr) * d + kk + 16 + ac4);
        }

#pragma unroll
        for (int k = 0; k < 16; k++) {
            u64 br0, br1, br2, br3, bi0, bi1, bi2, bi3, bs0, bs1, bs2, bs3;
            u64 a0, a1, a2, a3;
            lds2(br0, br1, &Bre[k][tn4]);
            lds2(br2, br3, &Bre[k][64 + tn4]);
            lds2(bi0, bi1, &Bim[k][tn4]);
            lds2(bi2, bi3, &Bim[k][64 + tn4]);
            add2(bs0, br0, bi0); add2(bs1, br1, bi1);
            add2(bs2, br2, bi2); add2(bs3, br3, bi3);

            lds2(a0, a1, &Adr[k][tm8]);
            lds2(a2, a3, &Adr[k][tm8 + 4]);
            fma2(T1[0][0], a0, br0); fma2(T1[0][1], a0, br1); fma2(T1[0][2], a0, br2); fma2(T1[0][3], a0, br3);
            fma2(T1[1][0], a1, br0); fma2(T1[1][1], a1, br1); fma2(T1[1][2], a1, br2); fma2(T1[1][3], a1, br3);
            fma2(T1[2][0], a2, br0); fma2(T1[2][1], a2, br1); fma2(T1[2][2], a2, br2); fma2(T1[2][3], a2, br3);
            fma2(T1[3][0], a3, br0); fma2(T1[3][1], a3, br1); fma2(T1[3][2], a3, br2); fma2(T1[3][3], a3, br3);

            lds2(a0, a1, &Adi[k][tm8]);
            lds2(a2, a3, &Adi[k][tm8 + 4]);
            fma2(T2[0][0], a0, bi0); fma2(T2[0][1], a0, bi1); fma2(T2[0][2], a0, bi2); fma2(T2[0][3], a0, bi3);
            fma2(T2[1][0], a1, bi0); fma2(T2[1][1], a1, bi1); fma2(T2[1][2], a1, bi2); fma2(T2[1][3], a1, bi3);
            fma2(T2[2][0], a2, bi0); fma2(T2[2][1], a2, bi1); fma2(T2[2][2], a2, bi2); fma2(T2[2][3], a2, bi3);
            fma2(T2[3][0], a3, bi0); fma2(T2[3][1], a3, bi1); fma2(T2[3][2], a3, bi2); fma2(T2[3][3], a3, bi3);

            lds2(a0, a1, &Ads[k][tm8]);
            lds2(a2, a3, &Ads[k][tm8 + 4]);
            fma2(T3[0][0], a0, bs0); fma2(T3[0][1], a0, bs1); fma2(T3[0][2], a0, bs2); fma2(T3[0][3], a0, bs3);
            fma2(T3[1][0], a1, bs0); fma2(T3[1][1], a1, bs1); fma2(T3[1][2], a1, bs2); fma2(T3[1][3], a1, bs3);
            fma2(T3[2][0], a2, bs0); fma2(T3[2][1], a2, bs1); fma2(T3[2][2], a2, bs2); fma2(T3[2][3], a2, bs3);
            fma2(T3[3][0], a3, bs0); fma2(T3[3][1], a3, bs1); fma2(T3[3][2], a3, bs2); fma2(T3[3][3], a3, bs3);
        }
        __syncthreads();
    }

#pragma unroll
    for (int i = 0; i < 4; i++) {
        int m = m0 + tm * 4 + i;
        float re[8], im_[8];
#pragma unroll
        for (int c = 0; c < 4; c++) {
            float t1l, t1h, t2l, t2h, t3l, t3h;
            unpack2(t1l, t1h, T1[i][c]);
            unpack2(t2l, t2h, T2[i][c]);
            unpack2(t3l, t3h, T3[i][c]);
            re[2 * c]     = t1l - t2l;
            re[2 * c + 1] = t1h - t2h;
            im_[2 * c]     = t3l - t1l - t2l;
            im_[2 * c + 1] = t3h - t1h - t2h;
        }
        *(float4*)(cre + (size_t)m * rest + tn4)      = make_float4(re[0], re[1], re[2], re[3]);
        *(float4*)(cre + (size_t)m * rest + 64 + tn4) = make_float4(re[4], re[5], re[6], re[7]);
        *(float4*)(cim + (size_t)m * rest + tn4)      = make_float4(im_[0], im_[1], im_[2], im_[3]);
        *(float4*)(cim + (size_t)m * rest + 64 + tn4) = make_float4(im_[4], im_[5], im_[6], im_[7]);
    }
}

// ============ NT split-K: P[chunk][b] = L[b] * U[b]^T (K chunk) ============
// tile: BM=64, BN=64, BK=16; 256 threads; per-thread 4(M) x 4(N)
__global__ __launch_bounds__(256, 2)
void cgemm_nt(const float* __restrict__ Lre, const float* __restrict__ Lim,
              const float* __restrict__ Ure, const float* __restrict__ Uim,
              float* __restrict__ Pre, float* __restrict__ Pim,
              int d, int K, int KC)
{
    __shared__ __align__(16) float Adr[16][NN_APAD], Adi[16][NN_APAD], Ads[16][NN_APAD];
    __shared__ __align__(16) float Bre[16][68], Bim[16][68];

    const int bz    = blockIdx.z;
    const int b     = bz & 7;
    const int chunk = bz >> 3;
    const int m0    = blockIdx.y * 64;
    const int n0    = blockIdx.x * 64;

    const float* lre = Lre + (size_t)b * d * K;
    const float* lim = Lim + (size_t)b * d * K;
    const float* ure = Ure + (size_t)b * d * K;
    const float* uim = Uim + (size_t)b * d * K;

    const int tid = threadIdx.x;
    const int tn4 = (tid & 15) * 4;
    const int tm  = tid >> 4;
    const int tm8 = tm * 8;
    const int lrr = tid >> 2;           // loader row 0..63 (both A and B)
    const int lc4 = (tid & 3) * 4;      // loader k-col

    u64 T1[4][2], T2[4][2], T3[4][2];
#pragma unroll
    for (int i = 0; i < 4; i++)
#pragma unroll
        for (int c = 0; c < 2; c++) { T1[i][c] = 0ULL; T2[i][c] = 0ULL; T3[i][c] = 0ULL; }

    const int kbeg = chunk * KC;
    const int kend = kbeg + KC;

    float4 par = *(const float4*)(lre + (size_t)(m0 + lrr) * K + kbeg + lc4);
    float4 pai = *(const float4*)(lim + (size_t)(m0 + lrr) * K + kbeg + lc4);
    float4 pbr = *(const float4*)(ure + (size_t)(n0 + lrr) * K + kbeg + lc4);
    float4 pbi = *(const float4*)(uim + (size_t)(n0 + lrr) * K + kbeg + lc4);

    for (int kk = kbeg; kk < kend; kk += 16) {
        {
            const float* pr = (const float*)&par;
            const float* pi = (const float*)&pai;
            const float* qr = (const float*)&pbr;
            const float* qi = (const float*)&pbi;
#pragma unroll
            for (int j = 0; j < 4; j++) {
                float vr = pr[j], vi = pi[j];
                *(float2*)&Adr[lc4 + j][2 * lrr] = make_float2(vr, vr);
                *(float2*)&Adi[lc4 + j][2 * lrr] = make_float2(vi, vi);
                float vs = vr + vi;
                *(float2*)&Ads[lc4 + j][2 * lrr] = make_float2(vs, vs);
                Bre[lc4 + j][lrr] = qr[j];
                Bim[lc4 + j][lrr] = qi[j];
            }
        }
        __syncthreads();

        if (kk + 16 < kend) {
            par = *(const float4*)(lre + (size_t)(m0 + lrr) * K + kk + 16 + lc4);
            pai = *(const float4*)(lim + (size_t)(m0 + lrr) * K + kk + 16 + lc4);
            pbr = *(const float4*)(ure + (size_t)(n0 + lrr) * K + kk + 16 + lc4);
            pbi = *(const float4*)(uim + (size_t)(n0 + lrr) * K + kk + 16 + lc4);
        }

#pragma unroll
        for (int k = 0; k < 16; k++) {
            u64 br0, br1, bi0, bi1, bs0, bs1, a0, a1, a2, a3;
            lds2(br0, br1, &Bre[k][tn4]);
            lds2(bi0, bi1, &Bim[k][tn4]);
            add2(bs0, br0, bi0); add2(bs1, br1, bi1);

            lds2(a0, a1, &Adr[k][tm8]);
            lds2(a2, a3, &Adr[k][tm8 + 4]);
            fma2(T1[0][0], a0, br0); fma2(T1[0][1], a0, br1);
            fma2(T1[1][0], a1, br0); fma2(T1[1][1], a1, br1);
            fma2(T1[2][0], a2, br0); fma2(T1[2][1], a2, br1);
            fma2(T1[3][0], a3, br0); fma2(T1[3][1], a3, br1);

            lds2(a0, a1, &Adi[k][tm8]);
            lds2(a2, a3, &Adi[k][tm8 + 4]);
            fma2(T2[0][0], a0, bi0); fma2(T2[0][1], a0, bi1);
            fma2(T2[1][0], a1, bi0); fma2(T2[1][1], a1, bi1);
            fma2(T2[2][0], a2, bi0); fma2(T2[2][1], a2, bi1);
            fma2(T2[3][0], a3, bi0); fma2(T2[3][1], a3, bi1);

            lds2(a0, a1, &Ads[k][tm8]);
            lds2(a2, a3, &Ads[k][tm8 + 4]);
            fma2(T3[0][0], a0, bs0); fma2(T3[0][1], a0, bs1);
            fma2(T3[1][0], a1, bs0); fma2(T3[1][1], a1, bs1);
            fma2(T3[2][0], a2, bs0); fma2(T3[2][1], a2, bs1);
            fma2(T3[3][0], a3, bs0); fma2(T3[3][1], a3, bs1);
        }
        __syncthreads();
    }

    size_t off = (size_t)(chunk * BATCH + b) * d * d;
#pragma unroll
    for (int i = 0; i < 4; i++) {
        int m = m0 + tm * 4 + i;
        float re[4], im_[4];
#pragma unroll
        for (int c = 0; c < 2; c++) {
            float t1l, t1h, t2l, t2h, t3l, t3h;
            unpack2(t1l, t1h, T1[i][c]);
            unpack2(t2l, t2h, T2[i][c]);
            unpack2(t3l, t3h, T3[i][c]);
            re[2 * c]     = t1l - t2l;
            re[2 * c + 1] = t1h - t2h;
            im_[2 * c]     = t3l - t1l - t2l;
            im_[2 * c + 1] = t3h - t1h - t2h;
        }
        *(float4*)(Pre + off + (size_t)m * d + n0 + tn4) = make_float4(re[0], re[1], re[2], re[3]);
        *(float4*)(Pim + off + (size_t)m * d + n0 + tn4) = make_float4(im_[0], im_[1], im_[2], im_[3]);
    }
}

// ---------------- fused split-K reduce + softmax(|s|/scale)*phase ---------
__global__ void softmax_fused(const float* __restrict__ Pre, const float* __restrict__ Pim,
                              float* __restrict__ Mre, float* __restrict__ Mim,
                              int d, int n, int nchunks,
                              const float* __restrict__ logtau, float sfac)
{
    const int row = blockIdx.x;
    const int j   = threadIdx.x;
    const int idx = row * d + j;

    float sr = 0.f, si = 0.f;
    for (int c = 0; c < nchunks; c++) {
        sr += Pre[(size_t)c * n + idx];
        si += Pim[(size_t)c * n + idx];
    }
    const float mag = sqrtf(sr * sr + si * si);

    const float tau   = fmaxf(expf(logtau[0]), 1e-8f);
    const float scale = tau * sfac;
    const float logit = mag / scale;

    __shared__ float wred[4];
    __shared__ float wsum[4];
    const int warp = j >> 5, lane = j & 31, nw = d >> 5;

    float v = logit;
#pragma unroll
    for (int o = 16; o > 0; o >>= 1) v = fmaxf(v, __shfl_xor_sync(0xffffffffu, v, o));
    if (lane == 0) wred[warp] = v;
    __syncthreads();
    float mx = wred[0];
    for (int w = 1; w < nw; w++) mx = fmaxf(mx, wred[w]);

    const float e = expf(logit - mx);
    float s_ = e;
#pragma unroll
    for (int o = 16; o > 0; o >>= 1) s_ += __shfl_xor_sync(0xffffffffu, s_, o);
    if (lane == 0) wsum[warp] = s_;
    __syncthreads();
    float tot = 0.f;
    for (int w = 0; w < nw; w++) tot += wsum[w];

    const float routing = e / tot;
    float pr, pi;
    if (mag > 1e-8f) { pr = sr / mag; pi = si / mag; }
    else             { pr = 1.f;      pi = 0.f; }
    Mre[(size_t)row * d + j] = routing * pr;
    Mim[(size_t)row * d + j] = routing * pi;
}

// ---------------- mode-1 permute (float4): swap the two 128-axes ----------
__global__ void perm_swap01(const float4* __restrict__ s4re, const float4* __restrict__ s4im,
                            float4* __restrict__ d4re, float4* __restrict__ d4im)
{
    int t = blockIdx.x * 256 + threadIdx.x;     // < NTOT/4 = 2097152
    int k4 = t & 15;
    int q  = (t >> 4) & 127;
    int p  = (t >> 11) & 127;
    int b  = t >> 18;
    int src = ((((b << 7) | q) << 7) | p) << 4 | k4;
    d4re[t] = s4re[src];
    d4im[t] = s4im[src];
}

// ---------------- batched 2D transpose: dst[b][c][r] = src[b][r][c] -------
__global__ void perm_transpose(const float* __restrict__ sre, const float* __restrict__ sim,
                               float* __restrict__ dre, float* __restrict__ dim_,
                               int R, int C)
{
    __shared__ float tre[32][33], tim[32][33];
    const int b  = blockIdx.z;
    const int r0 = blockIdx.y * 32;
    const int c0 = blockIdx.x * 32;
    const float* sr_ = sre + (size_t)b * R * C;
    const float* si_ = sim + (size_t)b * R * C;
    float*       dr_ = dre + (size_t)b * R * C;
    float*       di_ = dim_ + (size_t)b * R * C;
    const int x = threadIdx.x, y = threadIdx.y;    // 32 x 8
#pragma unroll
    for (int i = y; i < 32; i += 8) {
        tre[i][x] = sr_[(size_t)(r0 + i) * C + c0 + x];
        tim[i][x] = si_[(size_t)(r0 + i) * C + c0 + x];
    }
    __syncthreads();
#pragma unroll
    for (int i = y; i < 32; i += 8) {
        dr_[(size_t)(c0 + i) * R + r0 + x] = tre[x][i];
        di_[(size_t)(c0 + i) * R + r0 + x] = tim[x][i];
    }
}

// --------------------------------------------------------------------------
extern "C" void kernel_launch(void* const* d_in, const int* in_sizes, int n_in,
                              void* d_out, int out_size)
{
    (void)in_sizes; (void)n_in; (void)out_size;
    const float* xre  = (const float*)d_in[0];
    const float* xim  = (const float*)d_in[1];
    const float* w0re = (const float*)d_in[2];
    const float* w0im = (const float*)d_in[3];
    const float* w1re = (const float*)d_in[4];
    const float* w1im = (const float*)d_in[5];
    const float* w2re = (const float*)d_in[6];
    const float* w2im = (const float*)d_in[7];
    const float* ltau = (const float*)d_in[8];
    float* out_re = (float*)d_out;
    float* out_im = out_re + (size_t)NTOT;

    float *s_re, *s_im, *u_re, *u_im, *l_re, *l_im, *p_re, *p_im, *m_re, *m_im;
    cudaGetSymbolAddress((void**)&s_re,  g_s_re);
    cudaGetSymbolAddress((void**)&s_im,  g_s_im);
    cudaGetSymbolAddress((void**)&u_re,  g_u_re);
    cudaGetSymbolAddress((void**)&u_im,  g_u_im);
    cudaGetSymbolAddress((void**)&l_re,  g_l_re);
    cudaGetSymbolAddress((void**)&l_im,  g_l_im);
    cudaGetSymbolAddress((void**)&p_re,  g_p_re);
    cudaGetSymbolAddress((void**)&p_im,  g_p_im);
    cudaGetSymbolAddress((void**)&m_re,  g_m_re);
    cudaGetSymbolAddress((void**)&m_im,  g_m_im);

    // ---------------- Mode 0: d=128, rest=8192 (unfold = identity) --------
    {
        const int d = 128, rest = 8192;
        dim3 g1(rest / 128, d / 64, BATCH);
        cgemm_nn<<<g1, 256>>>(w0re, w0im, 0, xre, xim, l_re, l_im, d, rest);

        const int NC = 32, KC = rest / NC;        // 256
        dim3 g2(d / 64, d / 64, BATCH * NC);
        cgemm_nt<<<g2, 256>>>(l_re, l_im, xre, xim, p_re, p_im, d, rest, KC);

        const int n = BATCH * d * d;
        softmax_fused<<<BATCH * d, d>>>(p_re, p_im, m_re, m_im, d, n, NC, ltau,
                                        sqrtf((float)SS / (float)d));
        cgemm_nn<<<g1, 256>>>(m_re, m_im, d * d, xre, xim, s_re, s_im, d, rest);
    }

    // ---------------- Mode 1: d=128, rest=8192 ----------------------------
    {
        const int d = 128, rest = 8192;
        perm_swap01<<<(NTOT / 4) / 256, 256>>>((const float4*)s_re, (const float4*)s_im,
                                               (float4*)u_re, (float4*)u_im);

        dim3 g1(rest / 128, d / 64, BATCH);
        cgemm_nn<<<g1, 256>>>(w1re, w1im, 0, u_re, u_im, l_re, l_im, d, rest);

        const int NC = 32, KC = rest / NC;
        dim3 g2(d / 64, d / 64, BATCH * NC);
        cgemm_nt<<<g2, 256>>>(l_re, l_im, u_re, u_im, p_re, p_im, d, rest, KC);

        const int n = BATCH * d * d;
        softmax_fused<<<BATCH * d, d>>>(p_re, p_im, m_re, m_im, d, n, NC, ltau,
                                        sqrtf((float)SS / (float)d));
        cgemm_nn<<<g1, 256>>>(m_re, m_im, d * d, u_re, u_im, l_re, l_im, d, rest);
        perm_swap01<<<(NTOT / 4) / 256, 256>>>((const float4*)l_re, (const float4*)l_im,
                                               (float4*)s_re, (float4*)s_im);
    }

    // ---------------- Mode 2: d=64, rest=16384 ----------------------------
    {
        const int d = 64, rest = 16384;
        // unfold: u[b, k, p] = s[b, p, k]   (src R=16384, C=64)
        dim3 gt(64 / 32, 16384 / 32, BATCH);
        perm_transpose<<<gt, dim3(32, 8)>>>(s_re, s_im, u_re, u_im, 16384, 64);

        dim3 g1(rest / 128, d / 64, BATCH);
        cgemm_nn<<<g1, 256>>>(w2re, w2im, 0, u_re, u_im, l_re, l_im, d, rest);

        const int NC = 64, KC = rest / NC;        // 256
        dim3 g2(d / 64, d / 64, BATCH * NC);
        cgemm_nt<<<g2, 256>>>(l_re, l_im, u_re, u_im, p_re, p_im, d, rest, KC);

        const int n = BATCH * d * d;
        softmax_fused<<<BATCH * d, d>>>(p_re, p_im, m_re, m_im, d, n, NC, ltau,
                                        sqrtf((float)SS / (float)d));
        cgemm_nn<<<g1, 256>>>(m_re, m_im, d * d, u_re, u_im, l_re, l_im, d, rest);

        // fold: out[b, p, k] = mixed[b, k, p]   (src R=64, C=16384) -> d_out
        dim3 gt2(16384 / 32, 64 / 32, BATCH);
        perm_transpose<<<gt2, dim3(32, 8)>>>(l_re, l_im, out_re, out_im, 64, 16384);
    }
}